// round 16
// baseline (speedup 1.0000x reference)
#include <cuda_runtime.h>
#include <cuda_bf16.h>
#include <math.h>
#include <stdint.h>

#define S_TOK 4096
#define DE 256
#define DC 64
#define DIN 320
#define DM 64
#define DEPTH 4
#define DTs 0.1f
#define SCALE 0.0625f
#define KSPLIT 2
#define BM 64
#define BN 64
#define NT ((S_TOK/KSPLIT)/BN)   /* 32 key tiles per CTA */
#define SHIFT 20.0f
#define L2E 1.4426950408889634f

/* output layout offsets */
#define E_OFF  (S_TOK*DE)
#define P_OFF  (E_OFF + S_TOK)
#define G_OFF  (P_OFF + S_TOK)
#define M_OFF  (G_OFF + S_TOK)
#define C_OFF  (M_OFF + S_TOK*DM)
#define L_OFF  (C_OFF + S_TOK*DM)
#define A_OFF  (L_OFF + S_TOK)
#define D_OFF  (A_OFF + S_TOK)

/* attn SMEM map (bytes) */
#define SQH   0u
#define SQL   32768u
#define SKH   65536u
#define SKL   98304u
#define SVH   131072u
#define SVL   163840u
#define SMKH  196608u
#define SMKL  204800u
#define SPH   212992u
#define SPL   221184u      /* m~q lo staging; P hi/lo stored at SPH/SPL */
#define SLRED 229376u      /* 4 x 64 floats */
#define ATTN_SMEM_BYTES 230400u

/* qkv SMEM: x dbuf 4x8KB @0, W dbuf 4x16KB @32768 */
#define QKV_SMEM_BYTES 98304u

/* ------------------------- persistent device state ------------------- */
__device__ float g_e[S_TOK*DE];
__device__ __nv_bfloat16 g_xhi[S_TOK*DIN], g_xlo[S_TOK*DIN];   /* [e|c] split */
__device__ __nv_bfloat16 g_wthi[3*DEPTH*DE*DIN], g_wtlo[3*DEPTH*DE*DIN]; /* W^T [n][k] */
__device__ __nv_bfloat16 g_qhi[S_TOK*DE], g_qlo[S_TOK*DE];
__device__ __nv_bfloat16 g_khi[S_TOK*DE], g_klo[S_TOK*DE];
__device__ __nv_bfloat16 g_vthi[DE*S_TOK], g_vtlo[DE*S_TOK];   /* V^T [dim][tok] */
__device__ __nv_bfloat16 g_mthi[S_TOK*DM], g_mtlo[S_TOK*DM];   /* m~ = l*m split */
__device__ float g_m[S_TOK*DM];
__device__ float g_E[S_TOK], g_P[S_TOK], g_G[S_TOK], g_l[S_TOK];
__device__ float g_hpart[KSPLIT][S_TOK*DE];
__device__ float g_Lpart[KSPLIT][S_TOK];
__device__ int   g_alive_count;

/* ------------------------- mma / async helpers ------------------------ */
__device__ __forceinline__ uint32_t smem_to_u32(const void* p) {
    uint32_t a;
    asm("{ .reg .u64 t; cvta.to.shared.u64 t, %1; cvt.u32.u64 %0, t; }" : "=r"(a) : "l"(p));
    return a;
}
__device__ __forceinline__ void ldsm4(uint32_t a[4], uint32_t addr) {
    asm volatile("ldmatrix.sync.aligned.m8n8.x4.shared.b16 {%0,%1,%2,%3}, [%4];"
        : "=r"(a[0]), "=r"(a[1]), "=r"(a[2]), "=r"(a[3]) : "r"(addr));
}
__device__ __forceinline__ void mma16816(float c[4], const uint32_t a[4],
                                         uint32_t b0, uint32_t b1) {
    asm volatile("mma.sync.aligned.m16n8k16.row.col.f32.bf16.bf16.f32 "
        "{%0,%1,%2,%3}, {%4,%5,%6,%7}, {%8,%9}, {%0,%1,%2,%3};"
        : "+f"(c[0]), "+f"(c[1]), "+f"(c[2]), "+f"(c[3])
        : "r"(a[0]), "r"(a[1]), "r"(a[2]), "r"(a[3]), "r"(b0), "r"(b1));
}
__device__ __forceinline__ float ex2f(float x) {
    float r;
    asm("ex2.approx.f32 %0, %1;" : "=f"(r) : "f"(x));
    return r;
}
#define CP_ASYNC16(saddr, gptr) \
    asm volatile("cp.async.cg.shared.global [%0], [%1], 16;" \
                 :: "r"((uint32_t)(saddr)), "l"(gptr) : "memory")
#define CP_COMMIT() asm volatile("cp.async.commit_group;" ::: "memory")
#define CP_WAIT0()  asm volatile("cp.async.wait_group 0;" ::: "memory")
#define CP_WAIT1()  asm volatile("cp.async.wait_group 1;" ::: "memory")

/* swizzled smem address: rowBytes-stride tile, 16B chunks XORed by row&7 */
__device__ __forceinline__ uint32_t swa(uint32_t base, int r, int colElem, int rowBytes) {
    uint32_t ch = ((uint32_t)colElem >> 3) ^ ((uint32_t)r & 7u);
    return base + (uint32_t)(r * rowBytes) + (ch << 4);
}
__device__ __forceinline__ void split2(float v0, float v1, uint32_t& uh, uint32_t& ul) {
    __nv_bfloat162 h, l;
    h.x = __float2bfloat16(v0); h.y = __float2bfloat16(v1);
    l.x = __float2bfloat16(v0 - __bfloat162float(h.x));
    l.y = __float2bfloat16(v1 - __bfloat162float(h.y));
    uh = reinterpret_cast<uint32_t&>(h);
    ul = reinterpret_cast<uint32_t&>(l);
}

/* ------------------------------------------------------------------ init */
__global__ void init_kernel(const float* __restrict__ e, const float* __restrict__ Ein,
                            const float* __restrict__ Pin, const float* __restrict__ Gin,
                            const float* __restrict__ min_, const float* __restrict__ lin,
                            const float* __restrict__ cin)
{
    int i = blockIdx.x * 256 + threadIdx.x;      /* covers S_TOK*DE */
    {
        float v = e[i];
        g_e[i] = v;
        int tok = i >> 8, d = i & 255;
        __nv_bfloat16 h = __float2bfloat16(v);
        g_xhi[tok*DIN + d] = h;
        g_xlo[tok*DIN + d] = __float2bfloat16(v - __bfloat162float(h));
    }
    if (i < S_TOK*DC) {
        float v = cin[i];
        int tok = i >> 6, d = i & 63;
        __nv_bfloat16 h = __float2bfloat16(v);
        g_xhi[tok*DIN + 256 + d] = h;
        g_xlo[tok*DIN + 256 + d] = __float2bfloat16(v - __bfloat162float(h));
    }
    if (i < S_TOK*DM) {
        float mv = min_[i];
        g_m[i] = mv;
        float mt = mv * lin[i / DM];
        __nv_bfloat16 h = __float2bfloat16(mt);
        g_mthi[i] = h;
        g_mtlo[i] = __float2bfloat16(mt - __bfloat162float(h));
    }
    if (i < S_TOK) {
        g_l[i] = lin[i]; g_E[i] = Ein[i]; g_P[i] = Pin[i]; g_G[i] = Gin[i];
    }
    if (i == 0) g_alive_count = 0;
}

/* ---------------- coalesced weight transpose + split (once) ----------- */
__global__ void __launch_bounds__(256) wprep_kernel(
    const float* __restrict__ wq, const float* __restrict__ wk,
    const float* __restrict__ wv)
{
    __shared__ float sT[64][65];
    const int tid = threadIdx.x;
    const int k0 = blockIdx.x * 64, n0 = blockIdx.y * 64;
    const int which = blockIdx.z / DEPTH, layer = blockIdx.z % DEPTH;
    const float* W = (which == 0 ? wq : which == 1 ? wk : wv) + (size_t)layer * DIN * DE;
    const size_t wbase = ((size_t)which*DEPTH + layer) * DE * DIN;

    for (int idx = tid; idx < 64*64; idx += 256) {
        int kk = idx >> 6, nn = idx & 63;
        sT[nn][kk] = W[(size_t)(k0 + kk) * DE + n0 + nn];
    }
    __syncthreads();
    for (int idx = tid; idx < 64*64; idx += 256) {
        int nn = idx >> 6, kk = idx & 63;
        float v = sT[nn][kk];
        __nv_bfloat16 h = __float2bfloat16(v);
        g_wthi[wbase + (size_t)(n0 + nn)*DIN + k0 + kk] = h;
        g_wtlo[wbase + (size_t)(n0 + nn)*DIN + k0 + kk] =
            __float2bfloat16(v - __bfloat162float(h));
    }
}

/* ---------------- pipelined split-bf16 MMA QKV projections ------------ */
__global__ void __launch_bounds__(256) qkv_mma_kernel(
    const float* __restrict__ bq, const float* __restrict__ bk,
    const float* __restrict__ bv, int layer)
{
    extern __shared__ unsigned char smq[];
    const uint32_t sb = smem_to_u32(smq);
    const int tid = threadIdx.x;
    const int w = tid >> 5, lane = tid & 31;
    const int m0 = blockIdx.x * 64, n0 = blockIdx.y * 128;
    const int which = blockIdx.z;
    const float* B = (which == 0 ? bq : which == 1 ? bk : bv) + layer * DE;
    const size_t wbase = ((size_t)which*DEPTH + layer) * DE * DIN;
    const int lrow = lane & 15, lkh = (lane >> 4) * 8;
    const int lr = lane >> 2, qr = (lane & 3) * 2;
    const int r0 = (w >> 1) * 16, c0w = (w & 1) * 64;

    float acc[8][4];
    #pragma unroll
    for (int a = 0; a < 8; a++) { acc[a][0]=0.f; acc[a][1]=0.f; acc[a][2]=0.f; acc[a][3]=0.f; }

    #define QKV_ISSUE(t) do { \
        const int _b = (t) & 1; \
        const uint32_t _xh = (uint32_t)(_b * 16384); \
        const uint32_t _wh = 32768u + (uint32_t)(_b * 32768); \
        const int _k0 = (t) * 64; \
        for (int idx = tid; idx < 64*8; idx += 256) { \
            int r = idx >> 3, ch = idx & 7; \
            uint32_t dst = (uint32_t)ch ^ ((uint32_t)r & 7u); \
            CP_ASYNC16(sb + _xh        + r*128 + dst*16, g_xhi + (size_t)(m0 + r)*DIN + _k0 + ch*8); \
            CP_ASYNC16(sb + _xh + 8192 + r*128 + dst*16, g_xlo + (size_t)(m0 + r)*DIN + _k0 + ch*8); \
        } \
        for (int idx = tid; idx < 128*8; idx += 256) { \
            int r = idx >> 3, ch = idx & 7; \
            uint32_t dst = (uint32_t)ch ^ ((uint32_t)r & 7u); \
            CP_ASYNC16(sb + _wh         + r*128 + dst*16, g_wthi + wbase + (size_t)(n0 + r)*DIN + _k0 + ch*8); \
            CP_ASYNC16(sb + _wh + 16384 + r*128 + dst*16, g_wtlo + wbase + (size_t)(n0 + r)*DIN + _k0 + ch*8); \
        } \
        CP_COMMIT(); \
    } while (0)

    QKV_ISSUE(0);
    #pragma unroll 1
    for (int t = 0; t < 5; t++) {
        if (t < 4) { QKV_ISSUE(t + 1); CP_WAIT1(); }
        else       { CP_WAIT0(); }
        __syncthreads();
        const int b = t & 1;
        const uint32_t xh = (uint32_t)(b * 16384), xl = xh + 8192u;
        const uint32_t wh = 32768u + (uint32_t)(b * 32768), wl = wh + 16384u;
        #pragma unroll
        for (int kc = 0; kc < 4; kc++) {
            uint32_t ah[4], al[4];
            ldsm4(ah, swa(sb + xh, r0 + lrow, kc*16 + lkh, 128));
            ldsm4(al, swa(sb + xl, r0 + lrow, kc*16 + lkh, 128));
            #pragma unroll
            for (int g = 0; g < 4; g++) {
                uint32_t bh[4], bl[4];
                ldsm4(bh, swa(sb + wh, c0w + 16*g + lrow, kc*16 + lkh, 128));
                ldsm4(bl, swa(sb + wl, c0w + 16*g + lrow, kc*16 + lkh, 128));
                mma16816(acc[2*g],   ah, bh[0], bh[2]);
                mma16816(acc[2*g],   ah, bl[0], bl[2]);
                mma16816(acc[2*g],   al, bh[0], bh[2]);
                mma16816(acc[2*g+1], ah, bh[1], bh[3]);
                mma16816(acc[2*g+1], ah, bl[1], bl[3]);
                mma16816(acc[2*g+1], al, bh[1], bh[3]);
            }
        }
        __syncthreads();
    }

    if (which < 2) {
        __nv_bfloat16* ohi = (which == 0) ? g_qhi : g_khi;
        __nv_bfloat16* olo = (which == 0) ? g_qlo : g_klo;
        const int row = m0 + r0 + lr;
        #pragma unroll
        for (int a = 0; a < 8; a++) {
            const int col = n0 + c0w + 8*a + qr;
            float b0 = B[col], b1 = B[col+1];
            uint32_t uh, ul;
            split2(acc[a][0] + b0, acc[a][1] + b1, uh, ul);
            *(uint32_t*)(ohi + (size_t)row*DE + col) = uh;
            *(uint32_t*)(olo + (size_t)row*DE + col) = ul;
            split2(acc[a][2] + b0, acc[a][3] + b1, uh, ul);
            *(uint32_t*)(ohi + (size_t)(row+8)*DE + col) = uh;
            *(uint32_t*)(olo + (size_t)(row+8)*DE + col) = ul;
        }
    } else {
        /* V: bf16 hi/lo, transpose via smem (stride 80 elems = 160B) */
        __nv_bfloat16* th = (__nv_bfloat16*)smq;
        __nv_bfloat16* tl = th + 128*80;
        const int trow = r0 + lr;
        #pragma unroll
        for (int a = 0; a < 8; a++) {
            const int col = c0w + 8*a + qr;
            float b0 = B[n0 + col], b1 = B[n0 + col + 1];
            float v00 = acc[a][0] + b0, v01 = acc[a][1] + b1;
            float v10 = acc[a][2] + b0, v11 = acc[a][3] + b1;
            __nv_bfloat16 h;
            h = __float2bfloat16(v00); th[(col  )*80 + trow] = h;
            tl[(col  )*80 + trow] = __float2bfloat16(v00 - __bfloat162float(h));
            h = __float2bfloat16(v01); th[(col+1)*80 + trow] = h;
            tl[(col+1)*80 + trow] = __float2bfloat16(v01 - __bfloat162float(h));
            h = __float2bfloat16(v10); th[(col  )*80 + trow + 8] = h;
            tl[(col  )*80 + trow + 8] = __float2bfloat16(v10 - __bfloat162float(h));
            h = __float2bfloat16(v11); th[(col+1)*80 + trow + 8] = h;
            tl[(col+1)*80 + trow + 8] = __float2bfloat16(v11 - __bfloat162float(h));
        }
        __syncthreads();
        for (int idx = tid; idx < 128*8; idx += 256) {
            int r = idx >> 3, c = (idx & 7) * 8;
            *(uint4*)(g_vthi + (size_t)(n0 + r)*S_TOK + m0 + c) = *(const uint4*)(th + r*80 + c);
            *(uint4*)(g_vtlo + (size_t)(n0 + r)*S_TOK + m0 + c) = *(const uint4*)(tl + r*80 + c);
        }
    }
}

/* ---------- pipelined mma.sync flash attention, 16 warps/CTA ---------- */
__global__ void __launch_bounds__(512, 1) attn_kernel()
{
    extern __shared__ unsigned char sm[];
    const uint32_t sb = smem_to_u32(sm);
    float* sLred = (float*)(sm + SLRED);

    const int tid = threadIdx.x;
    const int w = tid >> 5, lane = tid & 31;
    const int row0 = blockIdx.x * BM;
    const int ks = blockIdx.y;
    const int key_base = ks * (S_TOK / KSPLIT);

    const int r0 = (w >> 2) * 16;          /* warp's 16 query rows          */
    const int cq = w & 3;                  /* warp's key quarter (scores)   */
    const int c0 = cq * 16;                /*   and dim quarter (AV)        */
    const int lr = lane >> 2;
    const int qr = (lane & 3) * 2;
    const int lrow = lane & 15, lkh = (lane >> 4) * 8;

    /* m~q staged in P region (plain stores) */
    for (int idx = tid; idx < 64*8; idx += 512) {
        int r = idx >> 3, ch = idx & 7;
        uint32_t dst = (uint32_t)ch ^ ((uint32_t)r & 7u);
        *(uint4*)(sm + SPH + r*128 + dst*16) = *(const uint4*)(g_mthi + (size_t)(row0 + r)*DM + ch*8);
        *(uint4*)(sm + SPL + r*128 + dst*16) = *(const uint4*)(g_mtlo + (size_t)(row0 + r)*DM + ch*8);
    }
    for (int idx = tid; idx < 64*32; idx += 512) {
        int r = idx >> 5, ch = idx & 31;
        uint32_t dst = (uint32_t)ch ^ ((uint32_t)r & 7u);
        CP_ASYNC16(sb + SQH + r*512 + dst*16, g_qhi + (size_t)(row0 + r)*DE + ch*8);
        CP_ASYNC16(sb + SQL + r*512 + dst*16, g_qlo + (size_t)(row0 + r)*DE + ch*8);
        CP_ASYNC16(sb + SKH + r*512 + dst*16, g_khi + (size_t)(key_base + r)*DE + ch*8);
        CP_ASYNC16(sb + SKL + r*512 + dst*16, g_klo + (size_t)(key_base + r)*DE + ch*8);
    }
    for (int idx = tid; idx < 64*8; idx += 512) {
        int r = idx >> 3, ch = idx & 7;
        uint32_t dst = (uint32_t)ch ^ ((uint32_t)r & 7u);
        CP_ASYNC16(sb + SMKH + r*128 + dst*16, g_mthi + (size_t)(key_base + r)*DM + ch*8);
        CP_ASYNC16(sb + SMKL + r*128 + dst*16, g_mtlo + (size_t)(key_base + r)*DM + ch*8);
    }
    CP_COMMIT();
    __syncthreads();   /* m~q stores visible (and first tile in flight) */

    /* copy m~q to dedicated region? not needed: P region reused after first
       score phase -- so hoist m~q fragments once now (8 ldsm, 16 regs) */
    uint32_t mqh[4][2], mql[4][2];
    #pragma unroll
    for (int kc = 0; kc < 4; kc++) {
        uint32_t t4[4];
        ldsm4(t4, swa(sb + SPH, r0 + lrow, kc*16 + lkh, 128));
        mqh[kc][0] = t4[0]; mqh[kc][1] = t4[1];
        /* x4 loads 16 rows: frags 2,3 are k8-15 */
        mqh[kc][0] = t4[0]; mqh[kc][1] = t4[1];
        uint32_t s4[4];
        ldsm4(s4, swa(sb + SPL, r0 + lrow, kc*16 + lkh, 128));
        /* keep full frags */
        mqh[kc][0] = t4[0]; mqh[kc][1] = t4[1];
        mql[kc][0] = s4[0]; mql[kc][1] = s4[1];
        /* store remaining halves in the other kc slot is wrong; use full arrays */
        /* (handled below with full-frag arrays) */
        (void)t4; (void)s4;
    }
    /* full-fragment m~q hoist (A frags are 4 regs each) */
    uint32_t mqfh[4][4], mqfl[4][4];
    #pragma unroll
    for (int kc = 0; kc < 4; kc++) {
        ldsm4(mqfh[kc], swa(sb + SPH, r0 + lrow, kc*16 + lkh, 128));
        ldsm4(mqfl[kc], swa(sb + SPL, r0 + lrow, kc*16 + lkh, 128));
    }

    float avacc[8][4];
    #pragma unroll
    for (int g = 0; g < 8; g++) { avacc[g][0]=0.f; avacc[g][1]=0.f; avacc[g][2]=0.f; avacc[g][3]=0.f; }
    float L0 = 0.f, L1 = 0.f;

    for (int kt = 0; kt < NT; kt++) {
        const int key0 = key_base + kt * BN;
        CP_WAIT0();
        __syncthreads();   /* K(kt)+mk(kt) ready; V buffer free */

        /* prefetch V^T(kt) while scores compute */
        for (int idx = tid; idx < 256*8; idx += 512) {
            int r = idx >> 3, ch = idx & 7;
            uint32_t dst = (uint32_t)ch ^ ((uint32_t)r & 7u);
            CP_ASYNC16(sb + SVH + r*128 + dst*16, g_vthi + (size_t)r*S_TOK + key0 + ch*8);
            CP_ASYNC16(sb + SVL + r*128 + dst*16, g_vtlo + (size_t)r*S_TOK + key0 + ch*8);
        }
        CP_COMMIT();

        /* ---- scores: 16 rows x 16 cols, qk (K=256) + mm (K=64) ---- */
        float sqk[2][4] = {}, smm[2][4] = {};
        #pragma unroll 2
        for (int kc = 0; kc < 16; kc++) {
            uint32_t ah[4], al[4], bh[4], bl[4];
            ldsm4(ah, swa(sb + SQH, r0 + lrow, kc*16 + lkh, 512));
            ldsm4(al, swa(sb + SQL, r0 + lrow, kc*16 + lkh, 512));
            ldsm4(bh, swa(sb + SKH, c0 + lrow, kc*16 + lkh, 512));
            ldsm4(bl, swa(sb + SKL, c0 + lrow, kc*16 + lkh, 512));
            mma16816(sqk[0], ah, bh[0], bh[2]);
            mma16816(sqk[0], ah, bl[0], bl[2]);
            mma16816(sqk[0], al, bh[0], bh[2]);
            mma16816(sqk[1], ah, bh[1], bh[3]);
            mma16816(sqk[1], ah, bl[1], bl[3]);
            mma16816(sqk[1], al, bh[1], bh[3]);
        }
        #pragma unroll
        for (int kc = 0; kc < 4; kc++) {
            uint32_t bh[4], bl[4];
            ldsm4(bh, swa(sb + SMKH, c0 + lrow, kc*16 + lkh, 128));
            ldsm4(bl, swa(sb + SMKL, c0 + lrow, kc*16 + lkh, 128));
            mma16816(smm[0], mqfh[kc], bh[0], bh[2]);
            mma16816(smm[0], mqfh[kc], bl[0], bl[2]);
            mma16816(smm[0], mqfl[kc], bh[0], bh[2]);
            mma16816(smm[1], mqfh[kc], bh[1], bh[3]);
            mma16816(smm[1], mqfh[kc], bl[1], bl[3]);
            mma16816(smm[1], mqfl[kc], bh[1], bh[3]);
        }

        /* ---- exp (fused const) + P store (bf16 hi/lo) ---- */
        {
            const int prow = r0 + lr;
            const float C1 = SCALE * L2E, C0 = -SHIFT * L2E;
            #pragma unroll
            for (int j = 0; j < 2; j++) {
                float p00 = ex2f(fmaf(sqk[j][0] * smm[j][0], C1, C0));
                float p01 = ex2f(fmaf(sqk[j][1] * smm[j][1], C1, C0));
                float p10 = ex2f(fmaf(sqk[j][2] * smm[j][2], C1, C0));
                float p11 = ex2f(fmaf(sqk[j][3] * smm[j][3], C1, C0));
                L0 += p00 + p01;
                L1 += p10 + p11;
                uint32_t uh0, ul0, uh1, ul1;
                split2(p00, p01, uh0, ul0);
                split2(p10, p11, uh1, ul1);
                uint32_t ch = (uint32_t)(cq*2 + j) ^ ((uint32_t)prow & 7u);
                uint32_t o0 = (uint32_t)prow*128 + (ch<<4) + (lane & 3)*4;
                uint32_t o1 = (uint32_t)(prow+8)*128 + (ch<<4) + (lane & 3)*4;
                *(uint32_t*)(sm + SPH + o0) = uh0;
                *(uint32_t*)(sm + SPL + o0) = ul0;
                *(uint32_t*)(sm + SPH + o1) = uh1;
                *(uint32_t*)(sm + SPL + o1) = ul1;
            }
        }
        CP_WAIT0();
        __syncthreads();   /* V^T(kt) ready; P visible; K reads done */

        /* prefetch K(kt+1)+mk(kt+1) while AV computes */
        if (kt + 1 < NT) {
            const int key1 = key0 + BN;
            for (int idx = tid; idx < 64*32; idx += 512) {
                int r = idx >> 5, ch = idx & 31;
                uint32_t dst = (uint32_t)ch ^ ((uint32_t)r & 7u);
                CP_ASYNC16(sb + SKH + r*512 + dst*16, g_khi + (size_t)(key1 + r)*DE + ch*8);
                CP_ASYNC16(sb + SKL + r*512 + dst*16, g_klo + (size_t)(key1 + r)*DE + ch*8);
            }
            for (int idx = tid; idx < 64*8; idx += 512) {
                int r = idx >> 3, ch = idx & 7;
                uint32_t dst = (uint32_t)ch ^ ((uint32_t)r & 7u);
                CP_ASYNC16(sb + SMKH + r*128 + dst*16, g_mthi + (size_t)(key1 + r)*DM + ch*8);
                CP_ASYNC16(sb + SMKL + r*128 + dst*16, g_mtlo + (size_t)(key1 + r)*DM + ch*8);
            }
        }
        CP_COMMIT();

        /* ---- AV: 16 rows x 64 dims (this warp's quarter), 64 keys ---- */
        #pragma unroll 2
        for (int kc = 0; kc < 4; kc++) {
            uint32_t ah[4], al[4];
            ldsm4(ah, swa(sb + SPH, r0 + lrow, kc*16 + lkh, 128));
            ldsm4(al, swa(sb + SPL, r0 + lrow, kc*16 + lkh, 128));
            #pragma unroll
            for (int gg = 0; gg < 4; gg++) {
                const int dd = cq*64 + 16*gg;
                uint32_t bh[4], bl[4];
                ldsm4(bh, swa(sb + SVH, dd + lrow, kc*16 + lkh, 128));
                ldsm4(bl, swa(sb + SVL, dd + lrow, kc*16 + lkh, 128));
                mma16816(avacc[2*gg],   ah, bh[0], bh[2]);
                mma16816(avacc[2*gg],   ah, bl[0], bl[2]);
                mma16816(avacc[2*gg],   al, bh[0], bh[2]);
                mma16816(avacc[2*gg+1], ah, bh[1], bh[3]);
                mma16816(avacc[2*gg+1], ah, bl[1], bl[3]);
                mma16816(avacc[2*gg+1], al, bh[1], bh[3]);
            }
        }
    }

    /* ---- epilogue: write partials + L ---- */
    {
        float* hp = g_hpart[ks];
        #pragma unroll
        for (int g = 0; g < 8; g++) {
            const int d = cq*64 + 8*g + qr;
            *(float2*)(hp + (size_t)(row0 + r0 + lr)*DE + d)     = make_float2(avacc[g][0], avacc[g][1]);
            *(float2*)(hp + (size_t)(row0 + r0 + lr + 8)*DE + d) = make_float2(avacc[g][2], avacc[g][3]);
        }
    }
    L0 += __shfl_xor_sync(0xffffffffu, L0, 1);
    L0 += __shfl_xor_sync(0xffffffffu, L0, 2);
    L1 += __shfl_xor_sync(0xffffffffu, L1, 1);
    L1 += __shfl_xor_sync(0xffffffffu, L1, 2);
    __syncthreads();
    if ((lane & 3) == 0) {
        sLred[cq*64 + r0 + lr]     = L0;
        sLred[cq*64 + r0 + lr + 8] = L1;
    }
    __syncthreads();
    if (tid < 64)
        g_Lpart[ks][row0 + tid] = sLred[tid] + sLred[64 + tid]
                                + sLred[128 + tid] + sLred[192 + tid];
}

/* ----------------------------------------- combine splits + ODE update */
__global__ void combine_kernel(const float* __restrict__ alpha, const float* __restrict__ beta,
                               const float* __restrict__ gamma, const float* __restrict__ basal,
                               int layer)
{
    const int s = blockIdx.x, tid = threadIdx.x;
    float Lt = 0.f, num = 0.f;
    #pragma unroll
    for (int k = 0; k < KSPLIT; k++) {
        Lt  += g_Lpart[k][s];
        num += g_hpart[k][(size_t)s*DE + tid];
    }
    const float h = num / Lt;
    const float e_new = g_e[(size_t)s*DE + tid] + h;
    g_e[(size_t)s*DE + tid] = e_new;
    {
        __nv_bfloat16 hh = __float2bfloat16(e_new);
        g_xhi[(size_t)s*DIN + tid] = hh;
        g_xlo[(size_t)s*DIN + tid] = __float2bfloat16(e_new - __bfloat162float(hh));
    }

    float part = h * h;
    #pragma unroll
    for (int off = 16; off; off >>= 1) part += __shfl_xor_sync(0xffffffffu, part, off);
    __shared__ float red[8];
    __shared__ float sc[2];
    if ((tid & 31) == 0) red[tid >> 5] = part;
    __syncthreads();
    if (tid == 0) {
        float S_in = red[0]+red[1]+red[2]+red[3]+red[4]+red[5]+red[6]+red[7];
        float E = g_E[s], P = g_P[s], Gv = g_G[s], l = g_l[s];
        float PE = P * E;
        float P_new = fmaxf(P + (alpha[layer]*S_in - beta[layer]*PE) * DTs, 0.f);
        float E_new = fmaxf(E + (basal[layer] - gamma[layer]*PE) * DTs, 0.f);
        float m_t = 1.f / (1.f + expf(-(E_new - P_new)));
        Gv += (0.1f*E_new - 0.5f*P_new) * DTs;
        float ldec = 0.01f + 0.5f*fmaxf(P_new - 2.f, 0.f);
        float l_new = fminf(fmaxf(l - ldec*DTs, 0.f), 1.f);
        g_E[s] = E_new; g_P[s] = P_new; g_G[s] = Gv; g_l[s] = l_new;
        sc[0] = m_t; sc[1] = l_new;
    }
    __syncthreads();
    if (tid < DM) {
        float mo = g_m[s*DM + tid];
        float mn = 0.9f*mo + 0.1f*sc[0];
        g_m[s*DM + tid] = mn;
        float mt = sc[1] * mn;
        __nv_bfloat16 hh = __float2bfloat16(mt);
        g_mthi[s*DM + tid] = hh;
        g_mtlo[s*DM + tid] = __float2bfloat16(mt - __bfloat162float(hh));
    }
}

/* -------------------------------------------------------- final output */
__global__ void output_kernel(const float* __restrict__ cin, float* __restrict__ out)
{
    const int s = blockIdx.x, tid = threadIdx.x;
    const float l = g_l[s];
    const bool alive = (l > 0.05f);
    const float af = alive ? 1.f : 0.f;
    out[(size_t)s*DE + tid] = g_e[(size_t)s*DE + tid] * af;
    if (tid < DM) {
        out[M_OFF + s*DM + tid] = g_m[s*DM + tid] * af;
        out[C_OFF + s*DM + tid] = cin[s*DM + tid] * af;
    }
    if (tid == 0) {
        out[E_OFF + s] = g_E[s] * af;
        out[P_OFF + s] = g_P[s] * af;
        out[G_OFF + s] = g_G[s] * af;
        out[L_OFF + s] = l * af;
        out[A_OFF + s] = af;
        if (alive) atomicAdd(&g_alive_count, 1);
    }
}

__global__ void died_kernel(float* __restrict__ out)
{
    out[D_OFF] = (float)(S_TOK - g_alive_count);
}

/* -------------------------------------------------------------- launch */
extern "C" void kernel_launch(void* const* d_in, const int* in_sizes, int n_in,
                              void* d_out, int out_size)
{
    const float* e     = (const float*)d_in[0];
    const float* Ein   = (const float*)d_in[1];
    const float* Pin   = (const float*)d_in[2];
    const float* Gin   = (const float*)d_in[3];
    const float* m     = (const float*)d_in[4];
    const float* c     = (const float*)d_in[5];
    const float* l     = (const float*)d_in[6];
    const float* wq    = (const float*)d_in[7];
    const float* bq    = (const float*)d_in[8];
    const float* wk    = (const float*)d_in[9];
    const float* bk    = (const float*)d_in[10];
    const float* wv    = (const float*)d_in[11];
    const float* bv    = (const float*)d_in[12];
    const float* alpha = (const float*)d_in[13];
    const float* beta  = (const float*)d_in[14];
    const float* gamma = (const float*)d_in[15];
    const float* basal = (const float*)d_in[16];
    float* out = (float*)d_out;

    cudaFuncSetAttribute(attn_kernel, cudaFuncAttributeMaxDynamicSharedMemorySize,
                         ATTN_SMEM_BYTES);
    cudaFuncSetAttribute(qkv_mma_kernel, cudaFuncAttributeMaxDynamicSharedMemorySize,
                         QKV_SMEM_BYTES);

    init_kernel<<<S_TOK*DE/256, 256>>>(e, Ein, Pin, Gin, m, l, c);
    wprep_kernel<<<dim3(DIN/64, DE/64, 3*DEPTH), 256>>>(wq, wk, wv);
    for (int layer = 0; layer < DEPTH; layer++) {
        qkv_mma_kernel<<<dim3(S_TOK/64, DE/128, 3), 256, QKV_SMEM_BYTES>>>(bq, bk, bv, layer);
        attn_kernel<<<dim3(S_TOK/BM, KSPLIT), 512, ATTN_SMEM_BYTES>>>();
        combine_kernel<<<S_TOK, 256>>>(alpha, beta, gamma, basal, layer);
    }
    output_kernel<<<S_TOK, 256>>>(c, out);
    died_kernel<<<1, 1>>>(out);
}

// round 17
// speedup vs baseline: 1.2733x; 1.2733x over previous
#include <cuda_runtime.h>
#include <cuda_bf16.h>
#include <math.h>
#include <stdint.h>

#define S_TOK 4096
#define DE 256
#define DC 64
#define DIN 320
#define DM 64
#define DEPTH 4
#define DTs 0.1f
#define SCALE 0.0625f
#define KSPLIT 2
#define BM 64
#define BN 64
#define NT ((S_TOK/KSPLIT)/BN)   /* 32 key tiles per CTA */
#define SHIFT 20.0f
#define L2E 1.4426950408889634f

/* output layout offsets */
#define E_OFF  (S_TOK*DE)
#define P_OFF  (E_OFF + S_TOK)
#define G_OFF  (P_OFF + S_TOK)
#define M_OFF  (G_OFF + S_TOK)
#define C_OFF  (M_OFF + S_TOK*DM)
#define L_OFF  (C_OFF + S_TOK*DM)
#define A_OFF  (L_OFF + S_TOK)
#define D_OFF  (A_OFF + S_TOK)

/* attn SMEM map (bytes) — V single buffer now */
#define SQH   0u
#define SQL   32768u
#define SKH   65536u
#define SKL   98304u
#define SVH   131072u      /* 256 rows x 128B = 32KB, single (bf16) */
#define SMKH  163840u
#define SMKL  172032u
#define SPH   180224u      /* P hi (single) / m~q hi staging */
#define SPL   188416u      /* m~q lo staging only */
#define SLRED 196608u
#define ATTN_SMEM_BYTES 197120u

/* qkv SMEM: x dbuf 4x8KB @0, W dbuf 4x16KB @32768 */
#define QKV_SMEM_BYTES 98304u

/* ------------------------- persistent device state ------------------- */
__device__ float g_e[S_TOK*DE];
__device__ __nv_bfloat16 g_xhi[S_TOK*DIN], g_xlo[S_TOK*DIN];   /* [e|c] split */
__device__ __nv_bfloat16 g_wthi[3*DEPTH*DE*DIN], g_wtlo[3*DEPTH*DE*DIN]; /* W^T [n][k] */
__device__ __nv_bfloat16 g_qhi[S_TOK*DE], g_qlo[S_TOK*DE];
__device__ __nv_bfloat16 g_khi[S_TOK*DE], g_klo[S_TOK*DE];
__device__ __nv_bfloat16 g_vt[DE*S_TOK];                       /* V^T single bf16 */
__device__ __nv_bfloat16 g_mthi[S_TOK*DM], g_mtlo[S_TOK*DM];   /* m~ = l*m split */
__device__ float g_m[S_TOK*DM];
__device__ float g_E[S_TOK], g_P[S_TOK], g_G[S_TOK], g_l[S_TOK];
__device__ float g_hpart[KSPLIT][S_TOK*DE];
__device__ float g_Lpart[KSPLIT][S_TOK];
__device__ int   g_alive_count;

/* ------------------------- mma / async helpers ------------------------ */
__device__ __forceinline__ uint32_t smem_to_u32(const void* p) {
    uint32_t a;
    asm("{ .reg .u64 t; cvta.to.shared.u64 t, %1; cvt.u32.u64 %0, t; }" : "=r"(a) : "l"(p));
    return a;
}
__device__ __forceinline__ void ldsm4(uint32_t a[4], uint32_t addr) {
    asm volatile("ldmatrix.sync.aligned.m8n8.x4.shared.b16 {%0,%1,%2,%3}, [%4];"
        : "=r"(a[0]), "=r"(a[1]), "=r"(a[2]), "=r"(a[3]) : "r"(addr));
}
__device__ __forceinline__ void mma16816(float c[4], const uint32_t a[4],
                                         uint32_t b0, uint32_t b1) {
    asm volatile("mma.sync.aligned.m16n8k16.row.col.f32.bf16.bf16.f32 "
        "{%0,%1,%2,%3}, {%4,%5,%6,%7}, {%8,%9}, {%0,%1,%2,%3};"
        : "+f"(c[0]), "+f"(c[1]), "+f"(c[2]), "+f"(c[3])
        : "r"(a[0]), "r"(a[1]), "r"(a[2]), "r"(a[3]), "r"(b0), "r"(b1));
}
__device__ __forceinline__ float ex2f(float x) {
    float r;
    asm("ex2.approx.f32 %0, %1;" : "=f"(r) : "f"(x));
    return r;
}
#define CP_ASYNC16(saddr, gptr) \
    asm volatile("cp.async.cg.shared.global [%0], [%1], 16;" \
                 :: "r"((uint32_t)(saddr)), "l"(gptr) : "memory")
#define CP_COMMIT() asm volatile("cp.async.commit_group;" ::: "memory")
#define CP_WAIT0()  asm volatile("cp.async.wait_group 0;" ::: "memory")
#define CP_WAIT1()  asm volatile("cp.async.wait_group 1;" ::: "memory")

/* swizzled smem address: rowBytes-stride tile, 16B chunks XORed by row&7 */
__device__ __forceinline__ uint32_t swa(uint32_t base, int r, int colElem, int rowBytes) {
    uint32_t ch = ((uint32_t)colElem >> 3) ^ ((uint32_t)r & 7u);
    return base + (uint32_t)(r * rowBytes) + (ch << 4);
}
__device__ __forceinline__ void split2(float v0, float v1, uint32_t& uh, uint32_t& ul) {
    __nv_bfloat162 h, l;
    h.x = __float2bfloat16(v0); h.y = __float2bfloat16(v1);
    l.x = __float2bfloat16(v0 - __bfloat162float(h.x));
    l.y = __float2bfloat16(v1 - __bfloat162float(h.y));
    uh = reinterpret_cast<uint32_t&>(h);
    ul = reinterpret_cast<uint32_t&>(l);
}

/* ------------------------------------------------------------------ init */
__global__ void init_kernel(const float* __restrict__ e, const float* __restrict__ Ein,
                            const float* __restrict__ Pin, const float* __restrict__ Gin,
                            const float* __restrict__ min_, const float* __restrict__ lin,
                            const float* __restrict__ cin)
{
    int i = blockIdx.x * 256 + threadIdx.x;      /* covers S_TOK*DE */
    {
        float v = e[i];
        g_e[i] = v;
        int tok = i >> 8, d = i & 255;
        __nv_bfloat16 h = __float2bfloat16(v);
        g_xhi[tok*DIN + d] = h;
        g_xlo[tok*DIN + d] = __float2bfloat16(v - __bfloat162float(h));
    }
    if (i < S_TOK*DC) {
        float v = cin[i];
        int tok = i >> 6, d = i & 63;
        __nv_bfloat16 h = __float2bfloat16(v);
        g_xhi[tok*DIN + 256 + d] = h;
        g_xlo[tok*DIN + 256 + d] = __float2bfloat16(v - __bfloat162float(h));
    }
    if (i < S_TOK*DM) {
        float mv = min_[i];
        g_m[i] = mv;
        float mt = mv * lin[i / DM];
        __nv_bfloat16 h = __float2bfloat16(mt);
        g_mthi[i] = h;
        g_mtlo[i] = __float2bfloat16(mt - __bfloat162float(h));
    }
    if (i < S_TOK) {
        g_l[i] = lin[i]; g_E[i] = Ein[i]; g_P[i] = Pin[i]; g_G[i] = Gin[i];
    }
    if (i == 0) g_alive_count = 0;
}

/* ---------------- coalesced weight transpose + split (once) ----------- */
__global__ void __launch_bounds__(256) wprep_kernel(
    const float* __restrict__ wq, const float* __restrict__ wk,
    const float* __restrict__ wv)
{
    __shared__ float sT[64][65];
    const int tid = threadIdx.x;
    const int k0 = blockIdx.x * 64, n0 = blockIdx.y * 64;
    const int which = blockIdx.z / DEPTH, layer = blockIdx.z % DEPTH;
    const float* W = (which == 0 ? wq : which == 1 ? wk : wv) + (size_t)layer * DIN * DE;
    const size_t wbase = ((size_t)which*DEPTH + layer) * DE * DIN;

    for (int idx = tid; idx < 64*64; idx += 256) {
        int kk = idx >> 6, nn = idx & 63;
        sT[nn][kk] = W[(size_t)(k0 + kk) * DE + n0 + nn];
    }
    __syncthreads();
    for (int idx = tid; idx < 64*64; idx += 256) {
        int nn = idx >> 6, kk = idx & 63;
        float v = sT[nn][kk];
        __nv_bfloat16 h = __float2bfloat16(v);
        g_wthi[wbase + (size_t)(n0 + nn)*DIN + k0 + kk] = h;
        g_wtlo[wbase + (size_t)(n0 + nn)*DIN + k0 + kk] =
            __float2bfloat16(v - __bfloat162float(h));
    }
}

/* ---------------- pipelined split-bf16 MMA QKV projections ------------ */
__global__ void __launch_bounds__(256) qkv_mma_kernel(
    const float* __restrict__ bq, const float* __restrict__ bk,
    const float* __restrict__ bv, int layer)
{
    extern __shared__ unsigned char smq[];
    const uint32_t sb = smem_to_u32(smq);
    const int tid = threadIdx.x;
    const int w = tid >> 5, lane = tid & 31;
    const int m0 = blockIdx.x * 64, n0 = blockIdx.y * 128;
    const int which = blockIdx.z;
    const float* B = (which == 0 ? bq : which == 1 ? bk : bv) + layer * DE;
    const size_t wbase = ((size_t)which*DEPTH + layer) * DE * DIN;
    const int lrow = lane & 15, lkh = (lane >> 4) * 8;
    const int lr = lane >> 2, qr = (lane & 3) * 2;
    const int r0 = (w >> 1) * 16, c0w = (w & 1) * 64;

    float acc[8][4];
    #pragma unroll
    for (int a = 0; a < 8; a++) { acc[a][0]=0.f; acc[a][1]=0.f; acc[a][2]=0.f; acc[a][3]=0.f; }

    #define QKV_ISSUE(t) do { \
        const int _b = (t) & 1; \
        const uint32_t _xh = (uint32_t)(_b * 16384); \
        const uint32_t _wh = 32768u + (uint32_t)(_b * 32768); \
        const int _k0 = (t) * 64; \
        for (int idx = tid; idx < 64*8; idx += 256) { \
            int r = idx >> 3, ch = idx & 7; \
            uint32_t dst = (uint32_t)ch ^ ((uint32_t)r & 7u); \
            CP_ASYNC16(sb + _xh        + r*128 + dst*16, g_xhi + (size_t)(m0 + r)*DIN + _k0 + ch*8); \
            CP_ASYNC16(sb + _xh + 8192 + r*128 + dst*16, g_xlo + (size_t)(m0 + r)*DIN + _k0 + ch*8); \
        } \
        for (int idx = tid; idx < 128*8; idx += 256) { \
            int r = idx >> 3, ch = idx & 7; \
            uint32_t dst = (uint32_t)ch ^ ((uint32_t)r & 7u); \
            CP_ASYNC16(sb + _wh         + r*128 + dst*16, g_wthi + wbase + (size_t)(n0 + r)*DIN + _k0 + ch*8); \
            CP_ASYNC16(sb + _wh + 16384 + r*128 + dst*16, g_wtlo + wbase + (size_t)(n0 + r)*DIN + _k0 + ch*8); \
        } \
        CP_COMMIT(); \
    } while (0)

    QKV_ISSUE(0);
    #pragma unroll 1
    for (int t = 0; t < 5; t++) {
        if (t < 4) { QKV_ISSUE(t + 1); CP_WAIT1(); }
        else       { CP_WAIT0(); }
        __syncthreads();
        const int b = t & 1;
        const uint32_t xh = (uint32_t)(b * 16384), xl = xh + 8192u;
        const uint32_t wh = 32768u + (uint32_t)(b * 32768), wl = wh + 16384u;
        #pragma unroll
        for (int kc = 0; kc < 4; kc++) {
            uint32_t ah[4], al[4];
            ldsm4(ah, swa(sb + xh, r0 + lrow, kc*16 + lkh, 128));
            ldsm4(al, swa(sb + xl, r0 + lrow, kc*16 + lkh, 128));
            #pragma unroll
            for (int g = 0; g < 4; g++) {
                uint32_t bh[4], bl[4];
                ldsm4(bh, swa(sb + wh, c0w + 16*g + lrow, kc*16 + lkh, 128));
                ldsm4(bl, swa(sb + wl, c0w + 16*g + lrow, kc*16 + lkh, 128));
                mma16816(acc[2*g],   ah, bh[0], bh[2]);
                mma16816(acc[2*g],   ah, bl[0], bl[2]);
                mma16816(acc[2*g],   al, bh[0], bh[2]);
                mma16816(acc[2*g+1], ah, bh[1], bh[3]);
                mma16816(acc[2*g+1], ah, bl[1], bl[3]);
                mma16816(acc[2*g+1], al, bh[1], bh[3]);
            }
        }
        __syncthreads();
    }

    if (which < 2) {
        __nv_bfloat16* ohi = (which == 0) ? g_qhi : g_khi;
        __nv_bfloat16* olo = (which == 0) ? g_qlo : g_klo;
        const int row = m0 + r0 + lr;
        #pragma unroll
        for (int a = 0; a < 8; a++) {
            const int col = n0 + c0w + 8*a + qr;
            float b0 = B[col], b1 = B[col+1];
            uint32_t uh, ul;
            split2(acc[a][0] + b0, acc[a][1] + b1, uh, ul);
            *(uint32_t*)(ohi + (size_t)row*DE + col) = uh;
            *(uint32_t*)(olo + (size_t)row*DE + col) = ul;
            split2(acc[a][2] + b0, acc[a][3] + b1, uh, ul);
            *(uint32_t*)(ohi + (size_t)(row+8)*DE + col) = uh;
            *(uint32_t*)(olo + (size_t)(row+8)*DE + col) = ul;
        }
    } else {
        /* V: single bf16, transpose via smem (stride 80 elems = 160B) */
        __nv_bfloat16* th = (__nv_bfloat16*)smq;
        const int trow = r0 + lr;
        #pragma unroll
        for (int a = 0; a < 8; a++) {
            const int col = c0w + 8*a + qr;
            float b0 = B[n0 + col], b1 = B[n0 + col + 1];
            th[(col  )*80 + trow]     = __float2bfloat16(acc[a][0] + b0);
            th[(col+1)*80 + trow]     = __float2bfloat16(acc[a][1] + b1);
            th[(col  )*80 + trow + 8] = __float2bfloat16(acc[a][2] + b0);
            th[(col+1)*80 + trow + 8] = __float2bfloat16(acc[a][3] + b1);
        }
        __syncthreads();
        for (int idx = tid; idx < 128*8; idx += 256) {
            int r = idx >> 3, c = (idx & 7) * 8;
            *(uint4*)(g_vt + (size_t)(n0 + r)*S_TOK + m0 + c) = *(const uint4*)(th + r*80 + c);
        }
    }
}

/* ------------------------- pipelined mma.sync flash attention --------- */
__global__ void __launch_bounds__(256, 1) attn_kernel()
{
    extern __shared__ unsigned char sm[];
    const uint32_t sb = smem_to_u32(sm);
    float* sLred = (float*)(sm + SLRED);

    const int tid = threadIdx.x;
    const int w = tid >> 5, lane = tid & 31;
    const int row0 = blockIdx.x * BM;
    const int ks = blockIdx.y;
    const int key_base = ks * (S_TOK / KSPLIT);

    const int r0 = (w >> 1) * 16;
    const int halfn = w & 1;
    const int c0 = halfn * 32;
    const int lr = lane >> 2;
    const int qr = (lane & 3) * 2;
    const int lrow = lane & 15, lkh = (lane >> 4) * 8;

    /* m~q staged in P region (plain stores) for one-time fragment hoist */
    for (int idx = tid; idx < 64*8; idx += 256) {
        int r = idx >> 3, ch = idx & 7;
        uint32_t dst = (uint32_t)ch ^ ((uint32_t)r & 7u);
        *(uint4*)(sm + SPH + r*128 + dst*16) = *(const uint4*)(g_mthi + (size_t)(row0 + r)*DM + ch*8);
        *(uint4*)(sm + SPL + r*128 + dst*16) = *(const uint4*)(g_mtlo + (size_t)(row0 + r)*DM + ch*8);
    }
    for (int idx = tid; idx < 64*32; idx += 256) {
        int r = idx >> 5, ch = idx & 31;
        uint32_t dst = (uint32_t)ch ^ ((uint32_t)r & 7u);
        CP_ASYNC16(sb + SQH + r*512 + dst*16, g_qhi + (size_t)(row0 + r)*DE + ch*8);
        CP_ASYNC16(sb + SQL + r*512 + dst*16, g_qlo + (size_t)(row0 + r)*DE + ch*8);
        CP_ASYNC16(sb + SKH + r*512 + dst*16, g_khi + (size_t)(key_base + r)*DE + ch*8);
        CP_ASYNC16(sb + SKL + r*512 + dst*16, g_klo + (size_t)(key_base + r)*DE + ch*8);
    }
    for (int idx = tid; idx < 64*8; idx += 256) {
        int r = idx >> 3, ch = idx & 7;
        uint32_t dst = (uint32_t)ch ^ ((uint32_t)r & 7u);
        CP_ASYNC16(sb + SMKH + r*128 + dst*16, g_mthi + (size_t)(key_base + r)*DM + ch*8);
        CP_ASYNC16(sb + SMKL + r*128 + dst*16, g_mtlo + (size_t)(key_base + r)*DM + ch*8);
    }
    CP_COMMIT();
    __syncthreads();

    uint32_t mqh[4][4], mql[4][4];
    #pragma unroll
    for (int kc = 0; kc < 4; kc++) {
        ldsm4(mqh[kc], swa(sb + SPH, r0 + lrow, kc*16 + lkh, 128));
        ldsm4(mql[kc], swa(sb + SPL, r0 + lrow, kc*16 + lkh, 128));
    }

    float avacc[16][4];
    #pragma unroll
    for (int g = 0; g < 16; g++) { avacc[g][0]=0.f; avacc[g][1]=0.f; avacc[g][2]=0.f; avacc[g][3]=0.f; }
    float L0 = 0.f, L1 = 0.f;

    for (int kt = 0; kt < NT; kt++) {
        const int key0 = key_base + kt * BN;
        CP_WAIT0();
        __syncthreads();

        /* prefetch V^T(kt) (single bf16) while scores compute */
        for (int idx = tid; idx < 256*8; idx += 256) {
            int r = idx >> 3, ch = idx & 7;
            uint32_t dst = (uint32_t)ch ^ ((uint32_t)r & 7u);
            CP_ASYNC16(sb + SVH + r*128 + dst*16, g_vt + (size_t)r*S_TOK + key0 + ch*8);
        }
        CP_COMMIT();

        float sqk[4][4] = {}, smm[4][4] = {};
        #pragma unroll 2
        for (int kc = 0; kc < 16; kc++) {
            uint32_t ah[4], al[4];
            ldsm4(ah, swa(sb + SQH, r0 + lrow, kc*16 + lkh, 512));
            ldsm4(al, swa(sb + SQL, r0 + lrow, kc*16 + lkh, 512));
            #pragma unroll
            for (int g = 0; g < 2; g++) {
                uint32_t bh[4], bl[4];
                ldsm4(bh, swa(sb + SKH, c0 + 16*g + lrow, kc*16 + lkh, 512));
                ldsm4(bl, swa(sb + SKL, c0 + 16*g + lrow, kc*16 + lkh, 512));
                mma16816(sqk[2*g],   ah, bh[0], bh[2]);
                mma16816(sqk[2*g],   ah, bl[0], bl[2]);
                mma16816(sqk[2*g],   al, bh[0], bh[2]);
                mma16816(sqk[2*g+1], ah, bh[1], bh[3]);
                mma16816(sqk[2*g+1], ah, bl[1], bl[3]);
                mma16816(sqk[2*g+1], al, bh[1], bh[3]);
            }
        }
        #pragma unroll
        for (int kc = 0; kc < 4; kc++) {
            #pragma unroll
            for (int g = 0; g < 2; g++) {
                uint32_t bh[4], bl[4];
                ldsm4(bh, swa(sb + SMKH, c0 + 16*g + lrow, kc*16 + lkh, 128));
                ldsm4(bl, swa(sb + SMKL, c0 + 16*g + lrow, kc*16 + lkh, 128));
                mma16816(smm[2*g],   mqh[kc], bh[0], bh[2]);
                mma16816(smm[2*g],   mqh[kc], bl[0], bl[2]);
                mma16816(smm[2*g],   mql[kc], bh[0], bh[2]);
                mma16816(smm[2*g+1], mqh[kc], bh[1], bh[3]);
                mma16816(smm[2*g+1], mqh[kc], bl[1], bl[3]);
                mma16816(smm[2*g+1], mql[kc], bh[1], bh[3]);
            }
        }

        /* ---- exp (fused const) + P store (single bf16); L from ROUNDED p */
        {
            const int prow = r0 + lr;
            const float C1 = SCALE * L2E, C0 = -SHIFT * L2E;
            #pragma unroll
            for (int j = 0; j < 4; j++) {
                float p00 = ex2f(fmaf(sqk[j][0] * smm[j][0], C1, C0));
                float p01 = ex2f(fmaf(sqk[j][1] * smm[j][1], C1, C0));
                float p10 = ex2f(fmaf(sqk[j][2] * smm[j][2], C1, C0));
                float p11 = ex2f(fmaf(sqk[j][3] * smm[j][3], C1, C0));
                __nv_bfloat162 h0, h1;
                h0.x = __float2bfloat16(p00); h0.y = __float2bfloat16(p01);
                h1.x = __float2bfloat16(p10); h1.y = __float2bfloat16(p11);
                L0 += __bfloat162float(h0.x) + __bfloat162float(h0.y);
                L1 += __bfloat162float(h1.x) + __bfloat162float(h1.y);
                uint32_t ch = (uint32_t)((c0 >> 3) + j) ^ ((uint32_t)prow & 7u);
                uint32_t o0 = (uint32_t)prow*128 + (ch<<4) + (lane & 3)*4;
                uint32_t o1 = (uint32_t)(prow+8)*128 + (ch<<4) + (lane & 3)*4;
                *(uint32_t*)(sm + SPH + o0) = reinterpret_cast<uint32_t&>(h0);
                *(uint32_t*)(sm + SPH + o1) = reinterpret_cast<uint32_t&>(h1);
            }
        }
        CP_WAIT0();
        __syncthreads();

        if (kt + 1 < NT) {
            const int key1 = key0 + BN;
            for (int idx = tid; idx < 64*32; idx += 256) {
                int r = idx >> 5, ch = idx & 31;
                uint32_t dst = (uint32_t)ch ^ ((uint32_t)r & 7u);
                CP_ASYNC16(sb + SKH + r*512 + dst*16, g_khi + (size_t)(key1 + r)*DE + ch*8);
                CP_ASYNC16(sb + SKL + r*512 + dst*16, g_klo + (size_t)(key1 + r)*DE + ch*8);
            }
            for (int idx = tid; idx < 64*8; idx += 256) {
                int r = idx >> 3, ch = idx & 7;
                uint32_t dst = (uint32_t)ch ^ ((uint32_t)r & 7u);
                CP_ASYNC16(sb + SMKH + r*128 + dst*16, g_mthi + (size_t)(key1 + r)*DM + ch*8);
                CP_ASYNC16(sb + SMKL + r*128 + dst*16, g_mtlo + (size_t)(key1 + r)*DM + ch*8);
            }
        }
        CP_COMMIT();

        /* ---- AV: single-bf16 P x single-bf16 V => 1 product ---- */
        #pragma unroll 2
        for (int kc = 0; kc < 4; kc++) {
            uint32_t ah[4];
            ldsm4(ah, swa(sb + SPH, r0 + lrow, kc*16 + lkh, 128));
            #pragma unroll
            for (int gg = 0; gg < 8; gg++) {
                const int dd = halfn*128 + 16*gg;
                uint32_t bh[4];
                ldsm4(bh, swa(sb + SVH, dd + lrow, kc*16 + lkh, 128));
                mma16816(avacc[2*gg],   ah, bh[0], bh[2]);
                mma16816(avacc[2*gg+1], ah, bh[1], bh[3]);
            }
        }
    }

    {
        float* hp = g_hpart[ks];
        #pragma unroll
        for (int g = 0; g < 16; g++) {
            const int d = halfn*128 + 8*g + qr;
            *(float2*)(hp + (size_t)(row0 + r0 + lr)*DE + d)     = make_float2(avacc[g][0], avacc[g][1]);
            *(float2*)(hp + (size_t)(row0 + r0 + lr + 8)*DE + d) = make_float2(avacc[g][2], avacc[g][3]);
        }
    }
    L0 += __shfl_xor_sync(0xffffffffu, L0, 1);
    L0 += __shfl_xor_sync(0xffffffffu, L0, 2);
    L1 += __shfl_xor_sync(0xffffffffu, L1, 1);
    L1 += __shfl_xor_sync(0xffffffffu, L1, 2);
    __syncthreads();
    if ((lane & 3) == 0) {
        sLred[halfn*64 + r0 + lr]     = L0;
        sLred[halfn*64 + r0 + lr + 8] = L1;
    }
    __syncthreads();
    if (tid < 64) g_Lpart[ks][row0 + tid] = sLred[tid] + sLred[64 + tid];
}

/* ----------------------------------------- combine splits + ODE update */
__global__ void combine_kernel(const float* __restrict__ alpha, const float* __restrict__ beta,
                               const float* __restrict__ gamma, const float* __restrict__ basal,
                               int layer)
{
    const int s = blockIdx.x, tid = threadIdx.x;
    float Lt = 0.f, num = 0.f;
    #pragma unroll
    for (int k = 0; k < KSPLIT; k++) {
        Lt  += g_Lpart[k][s];
        num += g_hpart[k][(size_t)s*DE + tid];
    }
    const float h = num / Lt;
    const float e_new = g_e[(size_t)s*DE + tid] + h;
    g_e[(size_t)s*DE + tid] = e_new;
    {
        __nv_bfloat16 hh = __float2bfloat16(e_new);
        g_xhi[(size_t)s*DIN + tid] = hh;
        g_xlo[(size_t)s*DIN + tid] = __float2bfloat16(e_new - __bfloat162float(hh));
    }

    float part = h * h;
    #pragma unroll
    for (int off = 16; off; off >>= 1) part += __shfl_xor_sync(0xffffffffu, part, off);
    __shared__ float red[8];
    __shared__ float sc[2];
    if ((tid & 31) == 0) red[tid >> 5] = part;
    __syncthreads();
    if (tid == 0) {
        float S_in = red[0]+red[1]+red[2]+red[3]+red[4]+red[5]+red[6]+red[7];
        float E = g_E[s], P = g_P[s], Gv = g_G[s], l = g_l[s];
        float PE = P * E;
        float P_new = fmaxf(P + (alpha[layer]*S_in - beta[layer]*PE) * DTs, 0.f);
        float E_new = fmaxf(E + (basal[layer] - gamma[layer]*PE) * DTs, 0.f);
        float m_t = 1.f / (1.f + expf(-(E_new - P_new)));
        Gv += (0.1f*E_new - 0.5f*P_new) * DTs;
        float ldec = 0.01f + 0.5f*fmaxf(P_new - 2.f, 0.f);
        float l_new = fminf(fmaxf(l - ldec*DTs, 0.f), 1.f);
        g_E[s] = E_new; g_P[s] = P_new; g_G[s] = Gv; g_l[s] = l_new;
        sc[0] = m_t; sc[1] = l_new;
    }
    __syncthreads();
    if (tid < DM) {
        float mo = g_m[s*DM + tid];
        float mn = 0.9f*mo + 0.1f*sc[0];
        g_m[s*DM + tid] = mn;
        float mt = sc[1] * mn;
        __nv_bfloat16 hh = __float2bfloat16(mt);
        g_mthi[s*DM + tid] = hh;
        g_mtlo[s*DM + tid] = __float2bfloat16(mt - __bfloat162float(hh));
    }
}

/* -------------------------------------------------------- final output */
__global__ void output_kernel(const float* __restrict__ cin, float* __restrict__ out)
{
    const int s = blockIdx.x, tid = threadIdx.x;
    const float l = g_l[s];
    const bool alive = (l > 0.05f);
    const float af = alive ? 1.f : 0.f;
    out[(size_t)s*DE + tid] = g_e[(size_t)s*DE + tid] * af;
    if (tid < DM) {
        out[M_OFF + s*DM + tid] = g_m[s*DM + tid] * af;
        out[C_OFF + s*DM + tid] = cin[s*DM + tid] * af;
    }
    if (tid == 0) {
        out[E_OFF + s] = g_E[s] * af;
        out[P_OFF + s] = g_P[s] * af;
        out[G_OFF + s] = g_G[s] * af;
        out[L_OFF + s] = l * af;
        out[A_OFF + s] = af;
        if (alive) atomicAdd(&g_alive_count, 1);
    }
}

__global__ void died_kernel(float* __restrict__ out)
{
    out[D_OFF] = (float)(S_TOK - g_alive_count);
}

/* -------------------------------------------------------------- launch */
extern "C" void kernel_launch(void* const* d_in, const int* in_sizes, int n_in,
                              void* d_out, int out_size)
{
    const float* e     = (const float*)d_in[0];
    const float* Ein   = (const float*)d_in[1];
    const float* Pin   = (const float*)d_in[2];
    const float* Gin   = (const float*)d_in[3];
    const float* m     = (const float*)d_in[4];
    const float* c     = (const float*)d_in[5];
    const float* l     = (const float*)d_in[6];
    const float* wq    = (const float*)d_in[7];
    const float* bq    = (const float*)d_in[8];
    const float* wk    = (const float*)d_in[9];
    const float* bk    = (const float*)d_in[10];
    const float* wv    = (const float*)d_in[11];
    const float* bv    = (const float*)d_in[12];
    const float* alpha = (const float*)d_in[13];
    const float* beta  = (const float*)d_in[14];
    const float* gamma = (const float*)d_in[15];
    const float* basal = (const float*)d_in[16];
    float* out = (float*)d_out;

    cudaFuncSetAttribute(attn_kernel, cudaFuncAttributeMaxDynamicSharedMemorySize,
                         ATTN_SMEM_BYTES);
    cudaFuncSetAttribute(qkv_mma_kernel, cudaFuncAttributeMaxDynamicSharedMemorySize,
                         QKV_SMEM_BYTES);

    init_kernel<<<S_TOK*DE/256, 256>>>(e, Ein, Pin, Gin, m, l, c);
    wprep_kernel<<<dim3(DIN/64, DE/64, 3*DEPTH), 256>>>(wq, wk, wv);
    for (int layer = 0; layer < DEPTH; layer++) {
        qkv_mma_kernel<<<dim3(S_TOK/64, DE/128, 3), 256, QKV_SMEM_BYTES>>>(bq, bk, bv, layer);
        attn_kernel<<<dim3(S_TOK/BM, KSPLIT), 256, ATTN_SMEM_BYTES>>>();
        combine_kernel<<<S_TOK, 256>>>(alpha, beta, gamma, basal, layer);
    }
    output_kernel<<<S_TOK, 256>>>(c, out);
    died_kernel<<<1, 1>>>(out);
}